// round 8
// baseline (speedup 1.0000x reference)
#include <cuda_runtime.h>
#include <math.h>

#define Bn 256
#define Fn 200
#define E1n 64
#define E2n 128
#define Hn 4
#define ALPHAc 0.2f
#define NEGc -9000000000000000.0f

#define TROWS 128                 // attention row tile (tiles: 128 + 72)
#define AP 132                    // attnT pad / reduction-buffer stride
#define KSPLIT 100                // y per warp-group

typedef unsigned long long ull;

// ---- packed f32x2 helpers ----
__device__ __forceinline__ ull dup2(float v) {
    ull r; asm("mov.b64 %0, {%1, %1};" : "=l"(r) : "f"(v)); return r;
}
__device__ __forceinline__ void fma2(ull &d, ull a, ull b) {
    asm("fma.rn.f32x2 %0, %1, %2, %0;" : "+l"(d) : "l"(a), "l"(b));
}
__device__ __forceinline__ void add2(ull &d, ull a) {
    asm("add.rn.f32x2 %0, %0, %1;" : "+l"(d) : "l"(a));
}
__device__ __forceinline__ float2 unpk(ull v) {
    float2 r; asm("mov.b64 {%0, %1}, %2;" : "=f"(r.x), "=f"(r.y) : "l"(v)); return r;
}
__device__ __forceinline__ ull d2l(double d) { return __double_as_longlong(d); }

// 8x8 f32x2 outer-product step: 8 dups + 32 fma2
#define GEMM_STEP(AV0, AV1, H0, H1)                                        \
    {                                                                      \
        ull hv0 = d2l(H0.x), hv1 = d2l(H0.y), hv2 = d2l(H1.x), hv3 = d2l(H1.y); \
        ull q0 = dup2(AV0.x), q1 = dup2(AV0.y), q2 = dup2(AV0.z), q3 = dup2(AV0.w); \
        ull q4 = dup2(AV1.x), q5 = dup2(AV1.y), q6 = dup2(AV1.z), q7 = dup2(AV1.w); \
        fma2(acc[0],  q0, hv0); fma2(acc[1],  q0, hv1); fma2(acc[2],  q0, hv2); fma2(acc[3],  q0, hv3); \
        fma2(acc[4],  q1, hv0); fma2(acc[5],  q1, hv1); fma2(acc[6],  q1, hv2); fma2(acc[7],  q1, hv3); \
        fma2(acc[8],  q2, hv0); fma2(acc[9],  q2, hv1); fma2(acc[10], q2, hv2); fma2(acc[11], q2, hv3); \
        fma2(acc[12], q3, hv0); fma2(acc[13], q3, hv1); fma2(acc[14], q3, hv2); fma2(acc[15], q3, hv3); \
        fma2(acc[16], q4, hv0); fma2(acc[17], q4, hv1); fma2(acc[18], q4, hv2); fma2(acc[19], q4, hv3); \
        fma2(acc[20], q5, hv0); fma2(acc[21], q5, hv1); fma2(acc[22], q5, hv2); fma2(acc[23], q5, hv3); \
        fma2(acc[24], q6, hv0); fma2(acc[25], q6, hv1); fma2(acc[26], q6, hv2); fma2(acc[27], q6, hv3); \
        fma2(acc[28], q7, hv0); fma2(acc[29], q7, hv1); fma2(acc[30], q7, hv2); fma2(acc[31], q7, hv3); \
    }

// ---------------------------------------------------------------------------
// Fused kernel: per CTA (h, b):
//   1. stage x[b] (200x64) + W[h] (64x128) into smem (aliased in attnT region)
//   2. proj: hs[200][128] = xs @ ws   (8x8 f32x2 tiles, 25 row-groups)
//   3. si/sj: warp-per-row dots of hs rows with a[h]
//   4. masked-softmax attention + attn @ hs (round-7 split-K structure)
// smem: hs 200x128 | region2: (xs 200x65 + ws 64x128) -> attnT 200x132
//       | sjs 200 | sis 200 | rscale 128   = 210,112 B
// ---------------------------------------------------------------------------
__global__ __launch_bounds__(512) void k_fused(const float* __restrict__ x,
                                               const float* __restrict__ adj,
                                               const float* __restrict__ W,
                                               const float* __restrict__ a,
                                               float* __restrict__ out) {
    extern __shared__ float smem[];
    float* hs     = smem;                   // [200][128] = 25600
    float* R      = smem + Fn*E2n;          // region2 base
    float* attnT  = R;                      // [200][AP] = 26400 (score/GEMM phases)
    float* xs     = R;                      // [200][65] = 13000 (proj phase only)
    float* ws     = R + 13000;              // [64][128] = 8192  (proj phase only)
    float* sjs    = R + Fn*AP;              // 200
    float* sis    = sjs + Fn;               // 200
    float* rscale = sis + Fn;               // 128

    int h = blockIdx.x, b = blockIdx.y;
    int tid = threadIdx.x;
    int warp = tid >> 5, lane = tid & 31;

    // ---- phase 1: stage xs (padded 65) and ws ----
    const float4* xg = (const float4*)(x + (size_t)b * Fn * E1n);
    for (int i = tid; i < Fn*E1n/4; i += 512) {      // 3200 float4s
        float4 v = xg[i];
        int r = i >> 4, c = (i & 15) << 2;
        float* p = &xs[r*65 + c];
        p[0] = v.x; p[1] = v.y; p[2] = v.z; p[3] = v.w;
    }
    const float4* wg = (const float4*)(W + (size_t)h * E1n * E2n);
    float4* ws4 = (float4*)ws;
    for (int i = tid; i < E1n*E2n/4; i += 512) ws4[i] = wg[i];
    __syncthreads();

    // ---- phase 2: proj GEMM hs = xs @ ws ----
    {
        int tr = tid >> 4;        // 0..31; rows tr*8..tr*8+7, active tr<25
        int tc = tid & 15;        // cols tc*8..tc*8+7
        if (tr < 25) {
            ull acc[32];
            #pragma unroll
            for (int i = 0; i < 32; ++i) acc[i] = 0ull;

            #pragma unroll 2
            for (int k = 0; k < E1n; ++k) {
                ull xd[8];
                #pragma unroll
                for (int r = 0; r < 8; ++r) xd[r] = dup2(xs[(tr*8 + r)*65 + k]);
                double2 w0 = *(const double2*)&ws[k*E2n + tc*8];
                double2 w1 = *(const double2*)&ws[k*E2n + tc*8 + 4];
                ull wv0 = d2l(w0.x), wv1 = d2l(w0.y), wv2 = d2l(w1.x), wv3 = d2l(w1.y);
                #pragma unroll
                for (int r = 0; r < 8; ++r) {
                    fma2(acc[r*4+0], xd[r], wv0);
                    fma2(acc[r*4+1], xd[r], wv1);
                    fma2(acc[r*4+2], xd[r], wv2);
                    fma2(acc[r*4+3], xd[r], wv3);
                }
            }
            #pragma unroll
            for (int r = 0; r < 8; ++r) {
                float2 v0 = unpk(acc[r*4+0]);
                float2 v1 = unpk(acc[r*4+1]);
                float2 v2 = unpk(acc[r*4+2]);
                float2 v3 = unpk(acc[r*4+3]);
                float* dp = &hs[(size_t)(tr*8 + r)*E2n + tc*8];
                *(float4*)dp       = make_float4(v0.x, v0.y, v1.x, v1.y);
                *(float4*)(dp + 4) = make_float4(v2.x, v2.y, v3.x, v3.y);
            }
        }
    }
    __syncthreads();     // hs complete; xs/ws dead

    // ---- phase 3: si/sj (warp per row) ----
    {
        const float* ap = a + (size_t)h * 2 * E2n;
        float4 aiv = *(const float4*)&ap[lane*4];
        float4 ajv = *(const float4*)&ap[E2n + lane*4];
        #pragma unroll 1
        for (int it = 0; it < 13; ++it) {
            int f = it*16 + warp;
            if (f < Fn) {
                float4 hv = *(const float4*)&hs[(size_t)f*E2n + lane*4];
                float pi = hv.x*aiv.x + hv.y*aiv.y + hv.z*aiv.z + hv.w*aiv.w;
                float pj = hv.x*ajv.x + hv.y*ajv.y + hv.z*ajv.z + hv.w*ajv.w;
                #pragma unroll
                for (int o = 16; o > 0; o >>= 1) {
                    pi += __shfl_xor_sync(0xffffffffu, pi, o);
                    pj += __shfl_xor_sync(0xffffffffu, pj, o);
                }
                if (lane == 0) { sis[f] = pi; sjs[f] = pj; }
            }
        }
    }
    __syncthreads();     // sis/sjs visible

    // ---- phase 4: attention (round-7 structure) ----
    int grp = tid >> 8;           // 0: y in [0,100), 1: y in [100,200)
    int gt  = tid & 255;
    int gtr = gt >> 4;            // rows gtr*8..gtr*8+7
    int gtc = gt & 15;            // cols gtc*8..gtc*8+7
    int y0  = grp * KSPLIT;

    for (int t0 = 0; t0 < Fn; t0 += TROWS) {
        int valid = Fn - t0; if (valid > TROWS) valid = TROWS;
        bool gemm_on = (gtr*8 < valid);

        // ---- score phase: 16 warps, row-pairs (rt0, rt0+16) ----
        #pragma unroll 1
        for (int p = 0; p < 4; ++p) {
            int rt0 = p*32 + warp;
            int rt1 = rt0 + 16;
            bool v0 = rt0 < valid, v1 = rt1 < valid;   // warp-uniform
            if (!v0) continue;

            int f0 = t0 + rt0, f1 = t0 + rt1;
            float si0 = sis[f0];
            float si1 = v1 ? sis[f1] : 0.f;
            const float* r0p = adj + (size_t)f0 * Fn;
            const float* r1p = adj + (size_t)f1 * Fn;

            float s0[7], s1[7];
            #pragma unroll
            for (int j = 0; j < 7; ++j) {
                int y = j*32 + lane;
                if (y < Fn) {
                    float sjv = sjs[y];
                    float m0 = r0p[y];
                    float z0 = si0 + sjv;
                    float e0 = (z0 > 0.f) ? z0 : ALPHAc * z0;
                    s0[j] = e0 * ((m0 > 0.f) ? m0 : NEGc);
                    if (v1) {
                        float m1 = r1p[y];
                        float z1 = si1 + sjv;
                        float e1 = (z1 > 0.f) ? z1 : ALPHAc * z1;
                        s1[j] = e1 * ((m1 > 0.f) ? m1 : NEGc);
                    } else s1[j] = -INFINITY;
                } else { s0[j] = -INFINITY; s1[j] = -INFINITY; }
            }

            float mx0 = s0[0], mx1 = s1[0];
            #pragma unroll
            for (int j = 1; j < 7; ++j) { mx0 = fmaxf(mx0, s0[j]); mx1 = fmaxf(mx1, s1[j]); }
            #pragma unroll
            for (int o = 16; o > 0; o >>= 1) {
                mx0 = fmaxf(mx0, __shfl_xor_sync(0xffffffffu, mx0, o));
                mx1 = fmaxf(mx1, __shfl_xor_sync(0xffffffffu, mx1, o));
            }
            float p0[7], p1[7], sum0 = 0.f, sum1 = 0.f;
            #pragma unroll
            for (int j = 0; j < 7; ++j) {
                p0[j] = __expf(s0[j] - mx0); sum0 += p0[j];
                p1[j] = __expf(s1[j] - mx1); sum1 += p1[j];
            }
            #pragma unroll
            for (int o = 16; o > 0; o >>= 1) {
                sum0 += __shfl_xor_sync(0xffffffffu, sum0, o);
                sum1 += __shfl_xor_sync(0xffffffffu, sum1, o);
            }
            #pragma unroll
            for (int j = 0; j < 7; ++j) {
                int y = j*32 + lane;
                if (y < Fn) {
                    attnT[y*AP + rt0] = p0[j];
                    if (v1) attnT[y*AP + rt1] = p1[j];
                }
            }
            if (lane == 0) {
                rscale[rt0] = 1.f / sum0;
                if (v1) rscale[rt1] = 1.f / sum1;
            }
        }
        __syncthreads();    // attnT + rscale visible

        // ---- GEMM: each group accumulates its y half (2-deep pipeline) ----
        ull acc[32];
        #pragma unroll
        for (int i = 0; i < 32; ++i) acc[i] = 0ull;

        if (gemm_on) {
            const float* aB = attnT + (size_t)y0*AP + gtr*8;
            const float* hB = hs + (size_t)y0*E2n + gtc*8;

            float4 avA0 = *(const float4*)&aB[0*AP];
            float4 avA1 = *(const float4*)&aB[0*AP + 4];
            double2 hA0 = *(const double2*)&hB[0*E2n];
            double2 hA1 = *(const double2*)&hB[0*E2n + 4];
            float4 avB0 = *(const float4*)&aB[1*AP];
            float4 avB1 = *(const float4*)&aB[1*AP + 4];
            double2 hB0 = *(const double2*)&hB[1*E2n];
            double2 hB1 = *(const double2*)&hB[1*E2n + 4];

            #pragma unroll 1
            for (int y = 0; y < KSPLIT - 2; y += 2) {
                GEMM_STEP(avA0, avA1, hA0, hA1);
                avA0 = *(const float4*)&aB[(y+2)*AP];
                avA1 = *(const float4*)&aB[(y+2)*AP + 4];
                hA0  = *(const double2*)&hB[(y+2)*E2n];
                hA1  = *(const double2*)&hB[(y+2)*E2n + 4];
                GEMM_STEP(avB0, avB1, hB0, hB1);
                avB0 = *(const float4*)&aB[(y+3)*AP];
                avB1 = *(const float4*)&aB[(y+3)*AP + 4];
                hB0  = *(const double2*)&hB[(y+3)*E2n];
                hB1  = *(const double2*)&hB[(y+3)*E2n + 4];
            }
            GEMM_STEP(avA0, avA1, hA0, hA1);
            GEMM_STEP(avB0, avB1, hB0, hB1);
        }
        __syncthreads();    // both groups done reading attnT

        // ---- reduction: group B parks partials in attnT region ----
        float* red = attnT;
        if (grp == 1 && gemm_on) {
            #pragma unroll
            for (int r = 0; r < 8; ++r) {
                float2 v0 = unpk(acc[r*4+0]);
                float2 v1 = unpk(acc[r*4+1]);
                float2 v2 = unpk(acc[r*4+2]);
                float2 v3 = unpk(acc[r*4+3]);
                float* rp = &red[(size_t)(gtr*8 + r)*AP + gtc*8];
                *(float4*)rp       = make_float4(v0.x, v0.y, v1.x, v1.y);
                *(float4*)(rp + 4) = make_float4(v2.x, v2.y, v3.x, v3.y);
            }
        }
        __syncthreads();    // partials visible

        // ---- group A: add partials, scale, store ----
        if (grp == 0 && gemm_on) {
            #pragma unroll
            for (int r = 0; r < 8; ++r) {
                int rt = gtr*8 + r;
                if (rt < valid) {
                    const float* rp = &red[(size_t)rt*AP + gtc*8];
                    double2 b0 = *(const double2*)rp;
                    double2 b1 = *(const double2*)(rp + 4);
                    add2(acc[r*4+0], d2l(b0.x));
                    add2(acc[r*4+1], d2l(b0.y));
                    add2(acc[r*4+2], d2l(b1.x));
                    add2(acc[r*4+3], d2l(b1.y));

                    int f = t0 + rt;
                    float sc = rscale[rt];
                    float2 v0 = unpk(acc[r*4+0]);
                    float2 v1 = unpk(acc[r*4+1]);
                    float2 v2 = unpk(acc[r*4+2]);
                    float2 v3 = unpk(acc[r*4+3]);
                    size_t o = ((size_t)b*Fn + f) * (Hn*E2n) + (size_t)h*E2n + gtc*8;
                    *(float4*)&out[o]     = make_float4(v0.x*sc, v0.y*sc, v1.x*sc, v1.y*sc);
                    *(float4*)&out[o + 4] = make_float4(v2.x*sc, v2.y*sc, v3.x*sc, v3.y*sc);
                }
            }
        }
        __syncthreads();   // attnT/rscale reuse by next tile
    }
}

// ---------------------------------------------------------------------------

extern "C" void kernel_launch(void* const* d_in, const int* in_sizes, int n_in,
                              void* d_out, int out_size) {
    const float* x   = (const float*)d_in[0];
    const float* adj = (const float*)d_in[1];
    const float* W   = (const float*)d_in[2];
    const float* a   = (const float*)d_in[3];
    float* out = (float*)d_out;

    const int SMEM_B = (Fn*E2n + Fn*AP + Fn + Fn + TROWS) * 4;     // 210,112 B
    cudaFuncSetAttribute(k_fused, cudaFuncAttributeMaxDynamicSharedMemorySize, SMEM_B);

    k_fused<<<dim3(Hn, Bn), 512, SMEM_B>>>(x, adj, W, a, out);     // 1,024 CTAs
}

// round 9
// speedup vs baseline: 1.0140x; 1.0140x over previous
#include <cuda_runtime.h>
#include <math.h>

#define Bn 256
#define Fn 200
#define E1n 64
#define E2n 128
#define Hn 4
#define ALPHAc 0.2f
#define NEGc -9000000000000000.0f

#define TROWS 128                 // attention row tile (tiles: 128 + 72)
#define AP 132                    // attnT pad / reduction-buffer stride
#define KSPLIT 100                // y per warp-group

typedef unsigned long long ull;

// ---- packed f32x2 helpers ----
__device__ __forceinline__ ull dup2(float v) {
    ull r; asm("mov.b64 %0, {%1, %1};" : "=l"(r) : "f"(v)); return r;
}
__device__ __forceinline__ void fma2(ull &d, ull a, ull b) {
    asm("fma.rn.f32x2 %0, %1, %2, %0;" : "+l"(d) : "l"(a), "l"(b));
}
__device__ __forceinline__ void add2(ull &d, ull a) {
    asm("add.rn.f32x2 %0, %0, %1;" : "+l"(d) : "l"(a));
}
__device__ __forceinline__ float2 unpk(ull v) {
    float2 r; asm("mov.b64 {%0, %1}, %2;" : "=f"(r.x), "=f"(r.y) : "l"(v)); return r;
}
__device__ __forceinline__ ull d2l(double d) { return __double_as_longlong(d); }

// 8x8 f32x2 outer-product step: 8 dups + 32 fma2
// hv0,hv1 = cols [c0, c0+4); hv2,hv3 = cols [c0+64, c0+68)
#define GEMM_STEP(AV0, AV1, H0, H1)                                        \
    {                                                                      \
        ull hv0 = d2l(H0.x), hv1 = d2l(H0.y), hv2 = d2l(H1.x), hv3 = d2l(H1.y); \
        ull q0 = dup2(AV0.x), q1 = dup2(AV0.y), q2 = dup2(AV0.z), q3 = dup2(AV0.w); \
        ull q4 = dup2(AV1.x), q5 = dup2(AV1.y), q6 = dup2(AV1.z), q7 = dup2(AV1.w); \
        fma2(acc[0],  q0, hv0); fma2(acc[1],  q0, hv1); fma2(acc[2],  q0, hv2); fma2(acc[3],  q0, hv3); \
        fma2(acc[4],  q1, hv0); fma2(acc[5],  q1, hv1); fma2(acc[6],  q1, hv2); fma2(acc[7],  q1, hv3); \
        fma2(acc[8],  q2, hv0); fma2(acc[9],  q2, hv1); fma2(acc[10], q2, hv2); fma2(acc[11], q2, hv3); \
        fma2(acc[12], q3, hv0); fma2(acc[13], q3, hv1); fma2(acc[14], q3, hv2); fma2(acc[15], q3, hv3); \
        fma2(acc[16], q4, hv0); fma2(acc[17], q4, hv1); fma2(acc[18], q4, hv2); fma2(acc[19], q4, hv3); \
        fma2(acc[20], q5, hv0); fma2(acc[21], q5, hv1); fma2(acc[22], q5, hv2); fma2(acc[23], q5, hv3); \
        fma2(acc[24], q6, hv0); fma2(acc[25], q6, hv1); fma2(acc[26], q6, hv2); fma2(acc[27], q6, hv3); \
        fma2(acc[28], q7, hv0); fma2(acc[29], q7, hv1); fma2(acc[30], q7, hv2); fma2(acc[31], q7, hv3); \
    }

// ---------------------------------------------------------------------------
// Fused kernel: per CTA (h, b):
//   1. stage x[b] (200x64) + W[h] (64x128) into smem (aliased in attnT region)
//   2. proj: hs[200][128] = xs @ ws
//   3. si/sj: warp-per-row dots of hs rows with a[h]
//   4. masked-softmax attention + attn @ hs (split-K over y)
// Column mapping everywhere: thread covers cols {c*4..+3} and {64+c*4..+3}
// so half-warp accesses are 256B-contiguous (bank-conflict-free-ish).
// ---------------------------------------------------------------------------
__global__ __launch_bounds__(512) void k_fused(const float* __restrict__ x,
                                               const float* __restrict__ adj,
                                               const float* __restrict__ W,
                                               const float* __restrict__ a,
                                               float* __restrict__ out) {
    extern __shared__ float smem[];
    float* hs     = smem;                   // [200][128] = 25600
    float* R      = smem + Fn*E2n;          // region2 base
    float* attnT  = R;                      // [200][AP] = 26400 (score/GEMM)
    float* xs     = R;                      // [200][65] = 13000 (proj only)
    float* ws     = R + 13000;              // [64][128] = 8192  (proj only)
    float* sjs    = R + Fn*AP;              // 200
    float* sis    = sjs + Fn;               // 200
    float* rscale = sis + Fn;               // 128

    int h = blockIdx.x, b = blockIdx.y;
    int tid = threadIdx.x;
    int warp = tid >> 5, lane = tid & 31;

    // ---- phase 1: stage xs (padded 65) and ws ----
    const float4* xg = (const float4*)(x + (size_t)b * Fn * E1n);
    for (int i = tid; i < Fn*E1n/4; i += 512) {
        float4 v = xg[i];
        int r = i >> 4, c = (i & 15) << 2;
        float* p = &xs[r*65 + c];
        p[0] = v.x; p[1] = v.y; p[2] = v.z; p[3] = v.w;
    }
    const float4* wg = (const float4*)(W + (size_t)h * E1n * E2n);
    float4* ws4 = (float4*)ws;
    for (int i = tid; i < E1n*E2n/4; i += 512) ws4[i] = wg[i];
    __syncthreads();

    // ---- phase 2: proj GEMM hs = xs @ ws (split-column mapping) ----
    {
        int tr = tid >> 4;        // 0..31; rows tr*8..tr*8+7, active tr<25
        int tc = tid & 15;        // cols tc*4..+3 and 64+tc*4..+3
        if (tr < 25) {
            ull acc[32];
            #pragma unroll
            for (int i = 0; i < 32; ++i) acc[i] = 0ull;

            #pragma unroll 2
            for (int k = 0; k < E1n; ++k) {
                ull xd[8];
                #pragma unroll
                for (int r = 0; r < 8; ++r) xd[r] = dup2(xs[(tr*8 + r)*65 + k]);
                double2 w0 = *(const double2*)&ws[k*E2n + tc*4];
                double2 w1 = *(const double2*)&ws[k*E2n + 64 + tc*4];
                ull wv0 = d2l(w0.x), wv1 = d2l(w0.y), wv2 = d2l(w1.x), wv3 = d2l(w1.y);
                #pragma unroll
                for (int r = 0; r < 8; ++r) {
                    fma2(acc[r*4+0], xd[r], wv0);
                    fma2(acc[r*4+1], xd[r], wv1);
                    fma2(acc[r*4+2], xd[r], wv2);
                    fma2(acc[r*4+3], xd[r], wv3);
                }
            }
            #pragma unroll
            for (int r = 0; r < 8; ++r) {
                float2 v0 = unpk(acc[r*4+0]);
                float2 v1 = unpk(acc[r*4+1]);
                float2 v2 = unpk(acc[r*4+2]);
                float2 v3 = unpk(acc[r*4+3]);
                float* dp = &hs[(size_t)(tr*8 + r)*E2n + tc*4];
                *(float4*)dp        = make_float4(v0.x, v0.y, v1.x, v1.y);
                *(float4*)(dp + 64) = make_float4(v2.x, v2.y, v3.x, v3.y);
            }
        }
    }
    __syncthreads();     // hs complete; xs/ws dead

    // ---- phase 3: si/sj (warp per row) ----
    {
        const float* ap = a + (size_t)h * 2 * E2n;
        float4 aiv = *(const float4*)&ap[lane*4];
        float4 ajv = *(const float4*)&ap[E2n + lane*4];
        #pragma unroll 1
        for (int it = 0; it < 13; ++it) {
            int f = it*16 + warp;
            if (f < Fn) {
                float4 hv = *(const float4*)&hs[(size_t)f*E2n + lane*4];
                float pi = hv.x*aiv.x + hv.y*aiv.y + hv.z*aiv.z + hv.w*aiv.w;
                float pj = hv.x*ajv.x + hv.y*ajv.y + hv.z*ajv.z + hv.w*ajv.w;
                #pragma unroll
                for (int o = 16; o > 0; o >>= 1) {
                    pi += __shfl_xor_sync(0xffffffffu, pi, o);
                    pj += __shfl_xor_sync(0xffffffffu, pj, o);
                }
                if (lane == 0) { sis[f] = pi; sjs[f] = pj; }
            }
        }
    }
    __syncthreads();     // sis/sjs visible

    // ---- phase 4: attention ----
    int grp = tid >> 8;           // 0: y in [0,100), 1: y in [100,200)
    int gt  = tid & 255;
    int gtr = gt >> 4;            // rows gtr*8..gtr*8+7
    int gtc = gt & 15;            // cols gtc*4..+3 and 64+gtc*4..+3
    int y0  = grp * KSPLIT;

    for (int t0 = 0; t0 < Fn; t0 += TROWS) {
        int valid = Fn - t0; if (valid > TROWS) valid = TROWS;
        bool gemm_on = (gtr*8 < valid);

        // ---- score phase: 16 warps, row-pairs (rt0, rt0+16) ----
        #pragma unroll 1
        for (int p = 0; p < 4; ++p) {
            int rt0 = p*32 + warp;
            int rt1 = rt0 + 16;
            bool v0 = rt0 < valid, v1 = rt1 < valid;   // warp-uniform
            if (!v0) continue;

            int f0 = t0 + rt0, f1 = t0 + rt1;
            float si0 = sis[f0];
            float si1 = v1 ? sis[f1] : 0.f;
            const float* r0p = adj + (size_t)f0 * Fn;
            const float* r1p = adj + (size_t)f1 * Fn;

            float s0[7], s1[7];
            #pragma unroll
            for (int j = 0; j < 7; ++j) {
                int y = j*32 + lane;
                if (y < Fn) {
                    float sjv = sjs[y];
                    float m0 = r0p[y];
                    float z0 = si0 + sjv;
                    float e0 = (z0 > 0.f) ? z0 : ALPHAc * z0;
                    s0[j] = e0 * ((m0 > 0.f) ? m0 : NEGc);
                    if (v1) {
                        float m1 = r1p[y];
                        float z1 = si1 + sjv;
                        float e1 = (z1 > 0.f) ? z1 : ALPHAc * z1;
                        s1[j] = e1 * ((m1 > 0.f) ? m1 : NEGc);
                    } else s1[j] = -INFINITY;
                } else { s0[j] = -INFINITY; s1[j] = -INFINITY; }
            }

            float mx0 = s0[0], mx1 = s1[0];
            #pragma unroll
            for (int j = 1; j < 7; ++j) { mx0 = fmaxf(mx0, s0[j]); mx1 = fmaxf(mx1, s1[j]); }
            #pragma unroll
            for (int o = 16; o > 0; o >>= 1) {
                mx0 = fmaxf(mx0, __shfl_xor_sync(0xffffffffu, mx0, o));
                mx1 = fmaxf(mx1, __shfl_xor_sync(0xffffffffu, mx1, o));
            }
            float p0[7], p1[7], sum0 = 0.f, sum1 = 0.f;
            #pragma unroll
            for (int j = 0; j < 7; ++j) {
                p0[j] = __expf(s0[j] - mx0); sum0 += p0[j];
                p1[j] = __expf(s1[j] - mx1); sum1 += p1[j];
            }
            #pragma unroll
            for (int o = 16; o > 0; o >>= 1) {
                sum0 += __shfl_xor_sync(0xffffffffu, sum0, o);
                sum1 += __shfl_xor_sync(0xffffffffu, sum1, o);
            }
            #pragma unroll
            for (int j = 0; j < 7; ++j) {
                int y = j*32 + lane;
                if (y < Fn) {
                    attnT[y*AP + rt0] = p0[j];
                    if (v1) attnT[y*AP + rt1] = p1[j];
                }
            }
            if (lane == 0) {
                rscale[rt0] = 1.f / sum0;
                if (v1) rscale[rt1] = 1.f / sum1;
            }
        }
        __syncthreads();    // attnT + rscale visible

        // ---- GEMM: each group accumulates its y half (2-deep pipeline) ----
        ull acc[32];
        #pragma unroll
        for (int i = 0; i < 32; ++i) acc[i] = 0ull;

        if (gemm_on) {
            const float* aB = attnT + (size_t)y0*AP + gtr*8;
            const float* hB = hs + (size_t)y0*E2n + gtc*4;

            float4 avA0 = *(const float4*)&aB[0*AP];
            float4 avA1 = *(const float4*)&aB[0*AP + 4];
            double2 hA0 = *(const double2*)&hB[0*E2n];
            double2 hA1 = *(const double2*)&hB[0*E2n + 64];
            float4 avB0 = *(const float4*)&aB[1*AP];
            float4 avB1 = *(const float4*)&aB[1*AP + 4];
            double2 hB0 = *(const double2*)&hB[1*E2n];
            double2 hB1 = *(const double2*)&hB[1*E2n + 64];

            #pragma unroll 1
            for (int y = 0; y < KSPLIT - 2; y += 2) {
                GEMM_STEP(avA0, avA1, hA0, hA1);
                avA0 = *(const float4*)&aB[(y+2)*AP];
                avA1 = *(const float4*)&aB[(y+2)*AP + 4];
                hA0  = *(const double2*)&hB[(y+2)*E2n];
                hA1  = *(const double2*)&hB[(y+2)*E2n + 64];
                GEMM_STEP(avB0, avB1, hB0, hB1);
                avB0 = *(const float4*)&aB[(y+3)*AP];
                avB1 = *(const float4*)&aB[(y+3)*AP + 4];
                hB0  = *(const double2*)&hB[(y+3)*E2n];
                hB1  = *(const double2*)&hB[(y+3)*E2n + 64];
            }
            GEMM_STEP(avA0, avA1, hA0, hA1);
            GEMM_STEP(avB0, avB1, hB0, hB1);
        }
        __syncthreads();    // both groups done reading attnT

        // ---- reduction: group B parks partials in attnT region ----
        float* red = attnT;
        if (grp == 1 && gemm_on) {
            #pragma unroll
            for (int r = 0; r < 8; ++r) {
                float2 v0 = unpk(acc[r*4+0]);
                float2 v1 = unpk(acc[r*4+1]);
                float2 v2 = unpk(acc[r*4+2]);
                float2 v3 = unpk(acc[r*4+3]);
                float* rp = &red[(size_t)(gtr*8 + r)*AP + gtc*4];
                *(float4*)rp        = make_float4(v0.x, v0.y, v1.x, v1.y);
                *(float4*)(rp + 64) = make_float4(v2.x, v2.y, v3.x, v3.y);
            }
        }
        __syncthreads();    // partials visible

        // ---- group A: add partials, scale, store ----
        if (grp == 0 && gemm_on) {
            #pragma unroll
            for (int r = 0; r < 8; ++r) {
                int rt = gtr*8 + r;
                if (rt < valid) {
                    const float* rp = &red[(size_t)rt*AP + gtc*4];
                    double2 b0 = *(const double2*)rp;
                    double2 b1 = *(const double2*)(rp + 64);
                    add2(acc[r*4+0], d2l(b0.x));
                    add2(acc[r*4+1], d2l(b0.y));
                    add2(acc[r*4+2], d2l(b1.x));
                    add2(acc[r*4+3], d2l(b1.y));

                    int f = t0 + rt;
                    float sc = rscale[rt];
                    float2 v0 = unpk(acc[r*4+0]);
                    float2 v1 = unpk(acc[r*4+1]);
                    float2 v2 = unpk(acc[r*4+2]);
                    float2 v3 = unpk(acc[r*4+3]);
                    size_t o = ((size_t)b*Fn + f) * (Hn*E2n) + (size_t)h*E2n + gtc*4;
                    *(float4*)&out[o]      = make_float4(v0.x*sc, v0.y*sc, v1.x*sc, v1.y*sc);
                    *(float4*)&out[o + 64] = make_float4(v2.x*sc, v2.y*sc, v3.x*sc, v3.y*sc);
                }
            }
        }
        __syncthreads();   // attnT/rscale reuse by next tile
    }
}

// ---------------------------------------------------------------------------

extern "C" void kernel_launch(void* const* d_in, const int* in_sizes, int n_in,
                              void* d_out, int out_size) {
    const float* x   = (const float*)d_in[0];
    const float* adj = (const float*)d_in[1];
    const float* W   = (const float*)d_in[2];
    const float* a   = (const float*)d_in[3];
    float* out = (float*)d_out;

    const int SMEM_B = (Fn*E2n + Fn*AP + Fn + Fn + TROWS) * 4;     // 210,112 B
    cudaFuncSetAttribute(k_fused, cudaFuncAttributeMaxDynamicSharedMemorySize, SMEM_B);

    k_fused<<<dim3(Hn, Bn), 512, SMEM_B>>>(x, adj, W, a, out);     // 1,024 CTAs
}

// round 10
// speedup vs baseline: 1.1134x; 1.0981x over previous
#include <cuda_runtime.h>
#include <math.h>

#define Bn 256
#define Fn 200
#define E1n 64
#define E2n 128
#define Hn 4
#define ALPHAc 0.2f
#define NEGc -9000000000000000.0f

#define TROWS 128                 // attention row tile (tiles: 128 + 72)
#define AP 132                    // attnT pad / reduction-buffer stride
#define KSPLIT 100                // y per warp-group

typedef unsigned long long ull;

// ---- packed f32x2 helpers ----
__device__ __forceinline__ ull dup2(float v) {
    ull r; asm("mov.b64 %0, {%1, %1};" : "=l"(r) : "f"(v)); return r;
}
__device__ __forceinline__ void fma2(ull &d, ull a, ull b) {
    asm("fma.rn.f32x2 %0, %1, %2, %0;" : "+l"(d) : "l"(a), "l"(b));
}
__device__ __forceinline__ void add2(ull &d, ull a) {
    asm("add.rn.f32x2 %0, %0, %1;" : "+l"(d) : "l"(a));
}
__device__ __forceinline__ float2 unpk(ull v) {
    float2 r; asm("mov.b64 {%0, %1}, %2;" : "=f"(r.x), "=f"(r.y) : "l"(v)); return r;
}
__device__ __forceinline__ ull d2l(double d) { return __double_as_longlong(d); }

// 8x8 f32x2 outer-product step, register-pressure-friendly:
// one dup temp live at a time (q), hv aliases the loaded double2 regs.
#define GEMM_STEP(AV0, AV1, H0, H1)                                        \
    {                                                                      \
        ull hv0 = d2l(H0.x), hv1 = d2l(H0.y), hv2 = d2l(H1.x), hv3 = d2l(H1.y); \
        ull q;                                                             \
        q = dup2(AV0.x); fma2(acc[0],  q, hv0); fma2(acc[1],  q, hv1); fma2(acc[2],  q, hv2); fma2(acc[3],  q, hv3); \
        q = dup2(AV0.y); fma2(acc[4],  q, hv0); fma2(acc[5],  q, hv1); fma2(acc[6],  q, hv2); fma2(acc[7],  q, hv3); \
        q = dup2(AV0.z); fma2(acc[8],  q, hv0); fma2(acc[9],  q, hv1); fma2(acc[10], q, hv2); fma2(acc[11], q, hv3); \
        q = dup2(AV0.w); fma2(acc[12], q, hv0); fma2(acc[13], q, hv1); fma2(acc[14], q, hv2); fma2(acc[15], q, hv3); \
        q = dup2(AV1.x); fma2(acc[16], q, hv0); fma2(acc[17], q, hv1); fma2(acc[18], q, hv2); fma2(acc[19], q, hv3); \
        q = dup2(AV1.y); fma2(acc[20], q, hv0); fma2(acc[21], q, hv1); fma2(acc[22], q, hv2); fma2(acc[23], q, hv3); \
        q = dup2(AV1.z); fma2(acc[24], q, hv0); fma2(acc[25], q, hv1); fma2(acc[26], q, hv2); fma2(acc[27], q, hv3); \
        q = dup2(AV1.w); fma2(acc[28], q, hv0); fma2(acc[29], q, hv1); fma2(acc[30], q, hv2); fma2(acc[31], q, hv3); \
    }

// ---------------------------------------------------------------------------
// Fused kernel: per CTA (h, b):
//   1. stage x[b] (200x64) + W[h] (64x128) into smem (aliased in attnT region)
//   2. proj: hs[200][128] = xs @ ws
//   3. si/sj: warp-per-row dots of hs rows with a[h]
//   4. masked-softmax attention + attn @ hs (split-K over y)
// Split-column mapping: thread covers cols {c*4..+3} and {64+c*4..+3}.
// ---------------------------------------------------------------------------
__global__ __launch_bounds__(512) void k_fused(const float* __restrict__ x,
                                               const float* __restrict__ adj,
                                               const float* __restrict__ W,
                                               const float* __restrict__ a,
                                               float* __restrict__ out) {
    extern __shared__ float smem[];
    float* hs     = smem;                   // [200][128] = 25600
    float* R      = smem + Fn*E2n;          // region2 base
    float* attnT  = R;                      // [200][AP] = 26400 (score/GEMM)
    float* xs     = R;                      // [200][65] = 13000 (proj only)
    float* ws     = R + 13000;              // [64][128] = 8192  (proj only)
    float* sjs    = R + Fn*AP;              // 200
    float* sis    = sjs + Fn;               // 200
    float* rscale = sis + Fn;               // 128

    int h = blockIdx.x, b = blockIdx.y;
    int tid = threadIdx.x;
    int warp = tid >> 5, lane = tid & 31;

    // ---- phase 1: stage xs (padded 65) and ws ----
    const float4* xg = (const float4*)(x + (size_t)b * Fn * E1n);
    for (int i = tid; i < Fn*E1n/4; i += 512) {
        float4 v = xg[i];
        int r = i >> 4, c = (i & 15) << 2;
        float* p = &xs[r*65 + c];
        p[0] = v.x; p[1] = v.y; p[2] = v.z; p[3] = v.w;
    }
    const float4* wg = (const float4*)(W + (size_t)h * E1n * E2n);
    float4* ws4 = (float4*)ws;
    for (int i = tid; i < E1n*E2n/4; i += 512) ws4[i] = wg[i];
    __syncthreads();

    // ---- phase 2: proj GEMM hs = xs @ ws (split-column mapping) ----
    {
        int tr = tid >> 4;        // 0..31; rows tr*8..tr*8+7, active tr<25
        int tc = tid & 15;        // cols tc*4..+3 and 64+tc*4..+3
        if (tr < 25) {
            ull acc[32];
            #pragma unroll
            for (int i = 0; i < 32; ++i) acc[i] = 0ull;

            #pragma unroll 2
            for (int k = 0; k < E1n; ++k) {
                double2 w0 = *(const double2*)&ws[k*E2n + tc*4];
                double2 w1 = *(const double2*)&ws[k*E2n + 64 + tc*4];
                ull wv0 = d2l(w0.x), wv1 = d2l(w0.y), wv2 = d2l(w1.x), wv3 = d2l(w1.y);
                ull q;
                #pragma unroll
                for (int r = 0; r < 8; ++r) {
                    q = dup2(xs[(tr*8 + r)*65 + k]);
                    fma2(acc[r*4+0], q, wv0);
                    fma2(acc[r*4+1], q, wv1);
                    fma2(acc[r*4+2], q, wv2);
                    fma2(acc[r*4+3], q, wv3);
                }
            }
            #pragma unroll
            for (int r = 0; r < 8; ++r) {
                float2 v0 = unpk(acc[r*4+0]);
                float2 v1 = unpk(acc[r*4+1]);
                float2 v2 = unpk(acc[r*4+2]);
                float2 v3 = unpk(acc[r*4+3]);
                float* dp = &hs[(size_t)(tr*8 + r)*E2n + tc*4];
                *(float4*)dp        = make_float4(v0.x, v0.y, v1.x, v1.y);
                *(float4*)(dp + 64) = make_float4(v2.x, v2.y, v3.x, v3.y);
            }
        }
    }
    __syncthreads();     // hs complete; xs/ws dead

    // ---- phase 3: si/sj (warp per row) ----
    {
        const float* ap = a + (size_t)h * 2 * E2n;
        float4 aiv = *(const float4*)&ap[lane*4];
        float4 ajv = *(const float4*)&ap[E2n + lane*4];
        #pragma unroll 1
        for (int it = 0; it < 13; ++it) {
            int f = it*16 + warp;
            if (f < Fn) {
                float4 hv = *(const float4*)&hs[(size_t)f*E2n + lane*4];
                float pi = hv.x*aiv.x + hv.y*aiv.y + hv.z*aiv.z + hv.w*aiv.w;
                float pj = hv.x*ajv.x + hv.y*ajv.y + hv.z*ajv.z + hv.w*ajv.w;
                #pragma unroll
                for (int o = 16; o > 0; o >>= 1) {
                    pi += __shfl_xor_sync(0xffffffffu, pi, o);
                    pj += __shfl_xor_sync(0xffffffffu, pj, o);
                }
                if (lane == 0) { sis[f] = pi; sjs[f] = pj; }
            }
        }
    }
    __syncthreads();     // sis/sjs visible

    // ---- phase 4: attention ----
    int grp = tid >> 8;           // 0: y in [0,100), 1: y in [100,200)
    int gt  = tid & 255;
    int gtr = gt >> 4;            // rows gtr*8..gtr*8+7
    int gtc = gt & 15;            // cols gtc*4..+3 and 64+gtc*4..+3
    int y0  = grp * KSPLIT;

    for (int t0 = 0; t0 < Fn; t0 += TROWS) {
        int valid = Fn - t0; if (valid > TROWS) valid = TROWS;
        bool gemm_on = (gtr*8 < valid);

        // ---- score phase: 16 warps, row-pairs (rt0, rt0+16) ----
        #pragma unroll 1
        for (int p = 0; p < 4; ++p) {
            int rt0 = p*32 + warp;
            int rt1 = rt0 + 16;
            bool v0 = rt0 < valid, v1 = rt1 < valid;   // warp-uniform
            if (!v0) continue;

            int f0 = t0 + rt0, f1 = t0 + rt1;
            float si0 = sis[f0];
            float si1 = v1 ? sis[f1] : 0.f;
            const float* r0p = adj + (size_t)f0 * Fn;
            const float* r1p = adj + (size_t)f1 * Fn;

            float s0[7], s1[7];
            #pragma unroll
            for (int j = 0; j < 7; ++j) {
                int y = j*32 + lane;
                if (y < Fn) {
                    float sjv = sjs[y];
                    float m0 = r0p[y];
                    float z0 = si0 + sjv;
                    float e0 = (z0 > 0.f) ? z0 : ALPHAc * z0;
                    s0[j] = e0 * ((m0 > 0.f) ? m0 : NEGc);
                    if (v1) {
                        float m1 = r1p[y];
                        float z1 = si1 + sjv;
                        float e1 = (z1 > 0.f) ? z1 : ALPHAc * z1;
                        s1[j] = e1 * ((m1 > 0.f) ? m1 : NEGc);
                    } else s1[j] = -INFINITY;
                } else { s0[j] = -INFINITY; s1[j] = -INFINITY; }
            }

            float mx0 = s0[0], mx1 = s1[0];
            #pragma unroll
            for (int j = 1; j < 7; ++j) { mx0 = fmaxf(mx0, s0[j]); mx1 = fmaxf(mx1, s1[j]); }
            #pragma unroll
            for (int o = 16; o > 0; o >>= 1) {
                mx0 = fmaxf(mx0, __shfl_xor_sync(0xffffffffu, mx0, o));
                mx1 = fmaxf(mx1, __shfl_xor_sync(0xffffffffu, mx1, o));
            }
            float p0[7], p1[7], sum0 = 0.f, sum1 = 0.f;
            #pragma unroll
            for (int j = 0; j < 7; ++j) {
                p0[j] = __expf(s0[j] - mx0); sum0 += p0[j];
                p1[j] = __expf(s1[j] - mx1); sum1 += p1[j];
            }
            #pragma unroll
            for (int o = 16; o > 0; o >>= 1) {
                sum0 += __shfl_xor_sync(0xffffffffu, sum0, o);
                sum1 += __shfl_xor_sync(0xffffffffu, sum1, o);
            }
            #pragma unroll
            for (int j = 0; j < 7; ++j) {
                int y = j*32 + lane;
                if (y < Fn) {
                    attnT[y*AP + rt0] = p0[j];
                    if (v1) attnT[y*AP + rt1] = p1[j];
                }
            }
            if (lane == 0) {
                rscale[rt0] = 1.f / sum0;
                if (v1) rscale[rt1] = 1.f / sum1;
            }
        }
        __syncthreads();    // attnT + rscale visible

        // ---- GEMM: each group accumulates its y half (depth-1 pipeline) ----
        ull acc[32];
        #pragma unroll
        for (int i = 0; i < 32; ++i) acc[i] = 0ull;

        if (gemm_on) {
            const float* pA = attnT + (size_t)y0*AP + gtr*8;
            const float* pH = hs + (size_t)y0*E2n + gtc*4;

            float4 aA0 = *(const float4*)&pA[0];
            float4 aA1 = *(const float4*)&pA[4];
            double2 hA0 = *(const double2*)&pH[0];
            double2 hA1 = *(const double2*)&pH[64];

            // Over-reads past y=KSPLIT-1 land in in-bounds dead smem and are
            // never consumed (loop exits); keeps the loop branch-free.
            #pragma unroll 1
            for (int y = 0; y < KSPLIT; y += 2) {
                float4 aB0 = *(const float4*)&pA[(y+1)*AP];
                float4 aB1 = *(const float4*)&pA[(y+1)*AP + 4];
                double2 hB0 = *(const double2*)&pH[(y+1)*E2n];
                double2 hB1 = *(const double2*)&pH[(y+1)*E2n + 64];
                GEMM_STEP(aA0, aA1, hA0, hA1);
                aA0 = *(const float4*)&pA[(y+2)*AP];
                aA1 = *(const float4*)&pA[(y+2)*AP + 4];
                hA0 = *(const double2*)&pH[(y+2)*E2n];
                hA1 = *(const double2*)&pH[(y+2)*E2n + 64];
                GEMM_STEP(aB0, aB1, hB0, hB1);
            }
        }
        __syncthreads();    // both groups done reading attnT

        // ---- reduction: group B parks partials in attnT region ----
        float* red = attnT;
        if (grp == 1 && gemm_on) {
            #pragma unroll
            for (int r = 0; r < 8; ++r) {
                float2 v0 = unpk(acc[r*4+0]);
                float2 v1 = unpk(acc[r*4+1]);
                float2 v2 = unpk(acc[r*4+2]);
                float2 v3 = unpk(acc[r*4+3]);
                float* rp = &red[(size_t)(gtr*8 + r)*AP + gtc*4];
                *(float4*)rp        = make_float4(v0.x, v0.y, v1.x, v1.y);
                *(float4*)(rp + 64) = make_float4(v2.x, v2.y, v3.x, v3.y);
            }
        }
        __syncthreads();    // partials visible

        // ---- group A: add partials, scale, store ----
        if (grp == 0 && gemm_on) {
            #pragma unroll
            for (int r = 0; r < 8; ++r) {
                int rt = gtr*8 + r;
                if (rt < valid) {
                    const float* rp = &red[(size_t)rt*AP + gtc*4];
                    double2 b0 = *(const double2*)rp;
                    double2 b1 = *(const double2*)(rp + 64);
                    add2(acc[r*4+0], d2l(b0.x));
                    add2(acc[r*4+1], d2l(b0.y));
                    add2(acc[r*4+2], d2l(b1.x));
                    add2(acc[r*4+3], d2l(b1.y));

                    int f = t0 + rt;
                    float sc = rscale[rt];
                    float2 v0 = unpk(acc[r*4+0]);
                    float2 v1 = unpk(acc[r*4+1]);
                    float2 v2 = unpk(acc[r*4+2]);
                    float2 v3 = unpk(acc[r*4+3]);
                    size_t o = ((size_t)b*Fn + f) * (Hn*E2n) + (size_t)h*E2n + gtc*4;
                    *(float4*)&out[o]      = make_float4(v0.x*sc, v0.y*sc, v1.x*sc, v1.y*sc);
                    *(float4*)&out[o + 64] = make_float4(v2.x*sc, v2.y*sc, v3.x*sc, v3.y*sc);
                }
            }
        }
        __syncthreads();   // attnT/rscale reuse by next tile
    }
}

// ---------------------------------------------------------------------------

extern "C" void kernel_launch(void* const* d_in, const int* in_sizes, int n_in,
                              void* d_out, int out_size) {
    const float* x   = (const float*)d_in[0];
    const float* adj = (const float*)d_in[1];
    const float* W   = (const float*)d_in[2];
    const float* a   = (const float*)d_in[3];
    float* out = (float*)d_out;

    const int SMEM_B = (Fn*E2n + Fn*AP + Fn + Fn + TROWS) * 4;     // 210,112 B
    cudaFuncSetAttribute(k_fused, cudaFuncAttributeMaxDynamicSharedMemorySize, SMEM_B);

    k_fused<<<dim3(Hn, Bn), 512, SMEM_B>>>(x, adj, W, a, out);     // 1,024 CTAs
}

// round 11
// speedup vs baseline: 1.2629x; 1.1342x over previous
#include <cuda_runtime.h>
#include <math.h>

#define Bn 256
#define Fn 200
#define E1n 64
#define E2n 128
#define Hn 4
#define ALPHAc 0.2f
#define NEGc -9000000000000000.0f

#define APW 68                    // attnT row width (tile rows <=64 + pad)
#define BUFSZ (Fn*APW)            // 13600 floats per prob buffer

typedef unsigned long long ull;

// ---- packed f32x2 helpers ----
__device__ __forceinline__ ull dup2(float v) {
    ull r; asm("mov.b64 %0, {%1, %1};" : "=l"(r) : "f"(v)); return r;
}
__device__ __forceinline__ void fma2(ull &d, ull a, ull b) {
    asm("fma.rn.f32x2 %0, %1, %2, %0;" : "+l"(d) : "l"(a), "l"(b));
}
__device__ __forceinline__ void add2(ull &d, ull a) {
    asm("add.rn.f32x2 %0, %0, %1;" : "+l"(d) : "l"(a));
}
__device__ __forceinline__ float2 unpk(ull v) {
    float2 r; asm("mov.b64 {%0, %1}, %2;" : "=f"(r.x), "=f"(r.y) : "l"(v)); return r;
}
__device__ __forceinline__ ull d2l(double d) { return __double_as_longlong(d); }

// 8 rows x 4 cols step: 8 dups + 16 fma2, one q temp live
#define STEP8(A0, A1, HV)                                                  \
    {                                                                      \
        ull h0 = d2l(HV.x), h1 = d2l(HV.y); ull q;                         \
        q = dup2(A0.x); fma2(acc[0],  q, h0); fma2(acc[1],  q, h1);        \
        q = dup2(A0.y); fma2(acc[2],  q, h0); fma2(acc[3],  q, h1);        \
        q = dup2(A0.z); fma2(acc[4],  q, h0); fma2(acc[5],  q, h1);        \
        q = dup2(A0.w); fma2(acc[6],  q, h0); fma2(acc[7],  q, h1);        \
        q = dup2(A1.x); fma2(acc[8],  q, h0); fma2(acc[9],  q, h1);        \
        q = dup2(A1.y); fma2(acc[10], q, h0); fma2(acc[11], q, h1);        \
        q = dup2(A1.z); fma2(acc[12], q, h0); fma2(acc[13], q, h1);        \
        q = dup2(A1.w); fma2(acc[14], q, h0); fma2(acc[15], q, h1);        \
    }

// ---------------------------------------------------------------------------
// Fused GAT kernel, CTA per (h, b):
//   proj -> si/sj -> [score(t+1) overlapped with GEMM(t)] over 4 row tiles.
// smem: hs[200][128] | bufs[2][200][APW] (alias xs+ws in proj) | sjs | sis
//       | rsc[2][64]  = 213,312 B  (1 CTA/SM, 512 threads)
// ---------------------------------------------------------------------------
__global__ __launch_bounds__(512) void k_fused(const float* __restrict__ x,
                                               const float* __restrict__ adj,
                                               const float* __restrict__ W,
                                               const float* __restrict__ a,
                                               float* __restrict__ out) {
    extern __shared__ float smem[];
    float* hs   = smem;                     // 25600
    float* bufs = smem + Fn*E2n;            // 2 * 13600
    float* sjs  = bufs + 2*BUFSZ;           // 200
    float* sis  = sjs + Fn;                 // 200
    float* rsc  = sis + Fn;                 // 2 * 64
    float* xs   = bufs;                     // alias (13000 floats, proj only)
    float* ws   = bufs + 13000;             // alias (8192 floats, proj only)

    int h = blockIdx.x, b = blockIdx.y;
    int tid = threadIdx.x;
    int warp = tid >> 5, lane = tid & 31;

    // ---- stage xs (padded 65) and ws ----
    const float4* xg = (const float4*)(x + (size_t)b * Fn * E1n);
    for (int i = tid; i < Fn*E1n/4; i += 512) {
        float4 v = xg[i];
        int r = i >> 4, c = (i & 15) << 2;
        float* p = &xs[r*65 + c];
        p[0] = v.x; p[1] = v.y; p[2] = v.z; p[3] = v.w;
    }
    const float4* wg = (const float4*)(W + (size_t)h * E1n * E2n);
    float4* ws4 = (float4*)ws;
    for (int i = tid; i < E1n*E2n/4; i += 512) ws4[i] = wg[i];
    __syncthreads();

    // ---- proj GEMM hs = xs @ ws (split-column mapping) ----
    {
        int tr = tid >> 4;        // 0..31; active tr<25
        int tc = tid & 15;
        if (tr < 25) {
            ull acc[32];
            #pragma unroll
            for (int i = 0; i < 32; ++i) acc[i] = 0ull;

            #pragma unroll 2
            for (int k = 0; k < E1n; ++k) {
                double2 w0 = *(const double2*)&ws[k*E2n + tc*4];
                double2 w1 = *(const double2*)&ws[k*E2n + 64 + tc*4];
                ull wv0 = d2l(w0.x), wv1 = d2l(w0.y), wv2 = d2l(w1.x), wv3 = d2l(w1.y);
                ull q;
                #pragma unroll
                for (int r = 0; r < 8; ++r) {
                    q = dup2(xs[(tr*8 + r)*65 + k]);
                    fma2(acc[r*4+0], q, wv0);
                    fma2(acc[r*4+1], q, wv1);
                    fma2(acc[r*4+2], q, wv2);
                    fma2(acc[r*4+3], q, wv3);
                }
            }
            #pragma unroll
            for (int r = 0; r < 8; ++r) {
                float2 v0 = unpk(acc[r*4+0]);
                float2 v1 = unpk(acc[r*4+1]);
                float2 v2 = unpk(acc[r*4+2]);
                float2 v3 = unpk(acc[r*4+3]);
                float* dp = &hs[(size_t)(tr*8 + r)*E2n + tc*4];
                *(float4*)dp        = make_float4(v0.x, v0.y, v1.x, v1.y);
                *(float4*)(dp + 64) = make_float4(v2.x, v2.y, v3.x, v3.y);
            }
        }
    }
    __syncthreads();     // hs complete; xs/ws dead

    // ---- si/sj (warp per row) ----
    {
        const float* ap = a + (size_t)h * 2 * E2n;
        float4 aiv = *(const float4*)&ap[lane*4];
        float4 ajv = *(const float4*)&ap[E2n + lane*4];
        #pragma unroll 1
        for (int it = 0; it < 13; ++it) {
            int f = it*16 + warp;
            if (f < Fn) {
                float4 hv = *(const float4*)&hs[(size_t)f*E2n + lane*4];
                float pi = hv.x*aiv.x + hv.y*aiv.y + hv.z*aiv.z + hv.w*aiv.w;
                float pj = hv.x*ajv.x + hv.y*ajv.y + hv.z*ajv.z + hv.w*ajv.w;
                #pragma unroll
                for (int o = 16; o > 0; o >>= 1) {
                    pi += __shfl_xor_sync(0xffffffffu, pi, o);
                    pj += __shfl_xor_sync(0xffffffffu, pj, o);
                }
                if (lane == 0) { sis[f] = pi; sjs[f] = pj; }
            }
        }
    }
    __syncthreads();     // sis/sjs visible

    // ---- score lambda: probs for rows [st0, st0+svalid) into bufW ----
    auto score_tile = [&](float* bufW, float* rscW, int st0, int svalid) {
        #pragma unroll 1
        for (int p = 0; p < 2; ++p) {
            int rt0 = p*32 + warp;
            int rt1 = rt0 + 16;
            bool v0 = rt0 < svalid, v1 = rt1 < svalid;   // warp-uniform
            if (!v0) continue;

            int f0 = st0 + rt0, f1 = st0 + rt1;
            float si0 = sis[f0];
            float si1 = v1 ? sis[f1] : 0.f;
            const float* r0p = adj + (size_t)f0 * Fn;
            const float* r1p = adj + (size_t)f1 * Fn;

            float s0[7], s1[7];
            #pragma unroll
            for (int j = 0; j < 7; ++j) {
                int y = j*32 + lane;
                if (y < Fn) {
                    float sjv = sjs[y];
                    float m0 = r0p[y];
                    float z0 = si0 + sjv;
                    float e0 = (z0 > 0.f) ? z0 : ALPHAc * z0;
                    s0[j] = e0 * ((m0 > 0.f) ? m0 : NEGc);
                    if (v1) {
                        float m1 = r1p[y];
                        float z1 = si1 + sjv;
                        float e1 = (z1 > 0.f) ? z1 : ALPHAc * z1;
                        s1[j] = e1 * ((m1 > 0.f) ? m1 : NEGc);
                    } else s1[j] = -INFINITY;
                } else { s0[j] = -INFINITY; s1[j] = -INFINITY; }
            }

            float mx0 = s0[0], mx1 = s1[0];
            #pragma unroll
            for (int j = 1; j < 7; ++j) { mx0 = fmaxf(mx0, s0[j]); mx1 = fmaxf(mx1, s1[j]); }
            #pragma unroll
            for (int o = 16; o > 0; o >>= 1) {
                mx0 = fmaxf(mx0, __shfl_xor_sync(0xffffffffu, mx0, o));
                mx1 = fmaxf(mx1, __shfl_xor_sync(0xffffffffu, mx1, o));
            }
            float p0[7], p1[7], sum0 = 0.f, sum1 = 0.f;
            #pragma unroll
            for (int j = 0; j < 7; ++j) {
                p0[j] = __expf(s0[j] - mx0); sum0 += p0[j];
                p1[j] = __expf(s1[j] - mx1); sum1 += p1[j];
            }
            #pragma unroll
            for (int o = 16; o > 0; o >>= 1) {
                sum0 += __shfl_xor_sync(0xffffffffu, sum0, o);
                sum1 += __shfl_xor_sync(0xffffffffu, sum1, o);
            }
            #pragma unroll
            for (int j = 0; j < 7; ++j) {
                int y = j*32 + lane;
                if (y < Fn) {
                    bufW[y*APW + rt0] = p0[j];
                    if (v1) bufW[y*APW + rt1] = p1[j];
                }
            }
            if (lane == 0) {
                rscW[rt0] = 1.f / sum0;
                if (v1) rscW[rt1] = 1.f / sum1;
            }
        }
    };

    // ---- attention: 4 tiles (64,64,64,8), score(t+1) overlapped w/ GEMM(t) ----
    int grp = tid >> 8;           // split-K: 0 -> y [0,100), 1 -> y [100,200)
    int gt  = tid & 255;
    int gtr = gt >> 5;            // 0..7 row-group (rows gtr*8..+7); == warp&7
    int y0  = grp * 100;

    score_tile(bufs, rsc, 0, 64);      // prologue: probs for tile 0
    __syncthreads();

    #pragma unroll 1
    for (int t = 0; t < 4; ++t) {
        int t0 = t*64;
        int valid = (t < 3) ? 64 : 8;
        float* bufR = bufs + (t&1)*BUFSZ;
        float* rscR = rsc + (t&1)*64;
        bool on = (gtr*8 < valid);

        ull acc[16];
        #pragma unroll
        for (int i = 0; i < 16; ++i) acc[i] = 0ull;

        if (on) {
            const float* pA = bufR + (size_t)y0*APW + gtr*8;
            const float* pH = hs + (size_t)y0*E2n + lane*4;

            float4 aA0 = *(const float4*)&pA[0];
            float4 aA1 = *(const float4*)&pA[4];
            double2 hA = *(const double2*)&pH[0];

            // over-reads at y=98 prefetch row 100 of the half: lands in
            // in-bounds smem (next buf / sjs region), never consumed.
            #pragma unroll 1
            for (int y = 0; y < 100; y += 2) {
                float4 aB0 = *(const float4*)&pA[(y+1)*APW];
                float4 aB1 = *(const float4*)&pA[(y+1)*APW + 4];
                double2 hB = *(const double2*)&pH[(y+1)*E2n];
                STEP8(aA0, aA1, hA);
                aA0 = *(const float4*)&pA[(y+2)*APW];
                aA1 = *(const float4*)&pA[(y+2)*APW + 4];
                hA  = *(const double2*)&pH[(y+2)*E2n];
                STEP8(aB0, aB1, hB);
            }
        }

        // overlapped: probs for next tile into the other buffer
        if (t < 3) score_tile(bufs + ((t+1)&1)*BUFSZ, rsc + ((t+1)&1)*64,
                              (t+1)*64, (t+1 < 3) ? 64 : 8);
        __syncthreads();    // GEMM reads of bufR done + next probs complete

        // group B parks partials into the consumed buffer
        if (grp == 1 && on) {
            #pragma unroll
            for (int r = 0; r < 8; ++r) {
                float2 v0 = unpk(acc[r*2+0]);
                float2 v1 = unpk(acc[r*2+1]);
                *(float4*)&bufR[(size_t)(gtr*8 + r)*E2n + lane*4] =
                    make_float4(v0.x, v0.y, v1.x, v1.y);
            }
        }
        __syncthreads();    // partials visible

        // group A: add partials, scale, store
        if (grp == 0 && on) {
            #pragma unroll
            for (int r = 0; r < 8; ++r) {
                int rt = gtr*8 + r;
                double2 pb = *(const double2*)&bufR[(size_t)rt*E2n + lane*4];
                add2(acc[r*2+0], d2l(pb.x));
                add2(acc[r*2+1], d2l(pb.y));
                float sc = rscR[rt];
                float2 v0 = unpk(acc[r*2+0]);
                float2 v1 = unpk(acc[r*2+1]);
                size_t o = ((size_t)b*Fn + t0 + rt) * (Hn*E2n) + (size_t)h*E2n + lane*4;
                *(float4*)&out[o] = make_float4(v0.x*sc, v0.y*sc, v1.x*sc, v1.y*sc);
            }
        }
        __syncthreads();    // bufR free for reuse as prob buffer (tile t+2)
    }
}

// ---------------------------------------------------------------------------

extern "C" void kernel_launch(void* const* d_in, const int* in_sizes, int n_in,
                              void* d_out, int out_size) {
    const float* x   = (const float*)d_in[0];
    const float* adj = (const float*)d_in[1];
    const float* W   = (const float*)d_in[2];
    const float* a   = (const float*)d_in[3];
    float* out = (float*)d_out;

    const int SMEM = (Fn*E2n + 2*BUFSZ + Fn + Fn + 2*64) * 4;   // 213,312 B
    cudaFuncSetAttribute(k_fused, cudaFuncAttributeMaxDynamicSharedMemorySize, SMEM);

    k_fused<<<dim3(Hn, Bn), 512, SMEM>>>(x, adj, W, a, out);    // 1,024 CTAs
}